// round 3
// baseline (speedup 1.0000x reference)
#include <cuda_runtime.h>
#include <math.h>

typedef unsigned long long ull;

#define NN_MAX 50000
#define NE_MAX 1000000

// ---- device-global scratch (no allocations allowed) ----
__device__ float g_s[NN_MAX];            // scalar feature per node
__device__ float g_v[NN_MAX * 6];        // vector features (2,3) per node
__device__ float g_vus[NN_MAX * 8];      // packed: [vu0.xyz, su, vu1.xyz, pad]
__device__ float g_agg[NN_MAX * 20];     // 18 used, padded to 20 (16B aligned)
__device__ float g_nhat[NE_MAX * 4];     // padded to float4
__device__ float g_radial[NE_MAX * 8];
__device__ float g_mix[NE_MAX * 8];

#define INV_SQRT2 0.70710678118654752f
#define INV_SQRT3 0.57735026918962576f
#define INV_SQRT5 0.44721359549995794f
#define INV_SQRT8 0.35355339059327376f
#define SQRT2_F   1.4142135623730951f
#define C121_F    2.1213203435596424f
#define SQRT3_F   1.7320508075688772f

__device__ __forceinline__ float swishf(float x) {
    return x / (1.0f + __expf(-x));
}

// ---- packed f32x2 helpers (SASS FFMA2 path, PTX-only) ----
__device__ __forceinline__ ull pack2(float x, float y) {
    ull r; asm("mov.b64 %0, {%1, %2};" : "=l"(r) : "f"(x), "f"(y)); return r;
}
__device__ __forceinline__ void unpack2(ull v, float& x, float& y) {
    asm("mov.b64 {%0, %1}, %2;" : "=f"(x), "=f"(y) : "l"(v));
}
__device__ __forceinline__ ull fma2(ull a, ull b, ull c) {
    ull d; asm("fma.rn.f32x2 %0, %1, %2, %3;" : "=l"(d) : "l"(a), "l"(b), "l"(c)); return d;
}
__device__ __forceinline__ ull mul2(ull a, ull b) {
    ull d; asm("mul.rn.f32x2 %0, %1, %2;" : "=l"(d) : "l"(a), "l"(b)); return d;
}
__device__ __forceinline__ ull swish2(ull a) {
    float x, y; unpack2(a, x, y);
    return pack2(swishf(x), swishf(y));
}

// ---------------------------------------------------------------------------
// init node state from node_features
// ---------------------------------------------------------------------------
__global__ void k_init(const float* __restrict__ nf, int nn) {
    int n = blockIdx.x * blockDim.x + threadIdx.x;
    if (n >= nn) return;
    g_s[n] = nf[n * 7];
#pragma unroll
    for (int i = 0; i < 6; i++) g_v[n * 6 + i] = nf[n * 7 + 1 + i];
}

// ---------------------------------------------------------------------------
// per-edge geometry: nhat (padded float4) + radial basis (8 features)
// ---------------------------------------------------------------------------
__global__ void k_geom(const float* __restrict__ pos,
                       const int* __restrict__ snd,
                       const int* __restrict__ rcv, int ne) {
    int e = blockIdx.x * blockDim.x + threadIdx.x;
    if (e >= ne) return;
    int s = snd[e], r = rcv[e];
    float vx = pos[r * 3 + 0] - pos[s * 3 + 0];
    float vy = pos[r * 3 + 1] - pos[s * 3 + 1];
    float vz = pos[r * 3 + 2] - pos[s * 3 + 2];
    float len = sqrtf(vx * vx + vy * vy + vz * vz);
    float inv = (len == 0.0f) ? 1.0f : (1.0f / len);
    *(float4*)&g_nhat[e * 4] = make_float4(vx * inv, vy * inv, vz * inv, 0.0f);

    float env = 0.0f;
    if (len < 1.0f) {
        float x = len;
        float x2 = x * x, x3 = x2 * x;
        float x6 = x3 * x3, x7 = x6 * x, x8 = x7 * x;
        env = 1.0f - 28.0f * x6 + 48.0f * x7 - 21.0f * x8;
    }
    float coef = (len == 0.0f) ? 0.0f : (SQRT2_F * env * inv);

    float s1, c1;
    sincospif(len, &s1, &c1);
    float out[8];
    float sm1 = 0.0f, sk = s1;
#pragma unroll
    for (int k = 0; k < 8; k++) {
        out[k] = sk * coef;
        float nx = 2.0f * c1 * sk - sm1;
        sm1 = sk; sk = nx;
    }
    *(float4*)&g_radial[e * 8]     = make_float4(out[0], out[1], out[2], out[3]);
    *(float4*)&g_radial[e * 8 + 4] = make_float4(out[4], out[5], out[6], out[7]);
}

// ---------------------------------------------------------------------------
// radial MLP, 2 edges/thread packed into f32x2 (FFMA2).
// Weights duplicated as float2 in smem so broadcast LDS.128 feeds 2 FFMA2s.
// i-outer structure: 64 packed accumulators, h1 computed on the fly.
// ---------------------------------------------------------------------------
__global__ __launch_bounds__(128) void k_mix(const float* __restrict__ W1,
                                             const float* __restrict__ W2,
                                             const float* __restrict__ W3,
                                             int ne) {
    __shared__ __align__(16) float2 sW1t[8 * 64];   // transposed: [i][m], dup
    __shared__ __align__(16) float2 sW2d[64 * 64];  // [i][j], dup (32 KB)
    __shared__ __align__(16) float2 sW3d[64 * 8];   // [j][k], dup
    for (int i = threadIdx.x; i < 512; i += 128) {
        int m = i & 7, ii = i >> 3;
        float w1 = W1[m * 64 + ii];           // sW1t[ii*8+m] = W1[m][ii]
        sW1t[i] = make_float2(w1, w1);
        float w3 = W3[i];
        sW3d[i] = make_float2(w3, w3);
    }
    for (int i = threadIdx.x; i < 4096; i += 128) {
        float w = W2[i];
        sW2d[i] = make_float2(w, w);
    }
    __syncthreads();

    int e0 = blockIdx.x * 256 + threadIdx.x;
    if (e0 >= ne) return;
    int e1 = e0 + 128;
    bool has1 = (e1 < ne);
    int e1c = has1 ? e1 : e0;

    float4 ra = *(const float4*)&g_radial[e0 * 8];
    float4 rb = *(const float4*)&g_radial[e0 * 8 + 4];
    float4 qa = *(const float4*)&g_radial[e1c * 8];
    float4 qb = *(const float4*)&g_radial[e1c * 8 + 4];
    ull rp[8] = { pack2(ra.x, qa.x), pack2(ra.y, qa.y), pack2(ra.z, qa.z), pack2(ra.w, qa.w),
                  pack2(rb.x, qb.x), pack2(rb.y, qb.y), pack2(rb.z, qb.z), pack2(rb.w, qb.w) };

    ull acc[64];
#pragma unroll
    for (int j = 0; j < 64; j++) acc[j] = 0ull;

    const ull cS8  = pack2(INV_SQRT8, INV_SQRT8);
    const ull c125 = pack2(0.125f, 0.125f);

#pragma unroll 2
    for (int i = 0; i < 64; i++) {
        // h1_i for both edges (packed)
        const ulonglong2* w1p = (const ulonglong2*)&sW1t[i * 8];
        ull h = 0ull;
#pragma unroll
        for (int m2 = 0; m2 < 4; m2++) {
            ulonglong2 ww = w1p[m2];
            h = fma2(rp[2 * m2 + 0], ww.x, h);
            h = fma2(rp[2 * m2 + 1], ww.y, h);
        }
        h = swish2(mul2(h, cS8));
        // sweep row i of W2: 32 LDS.128 + 64 FFMA2
        const ulonglong2* w2p = (const ulonglong2*)&sW2d[i * 64];
#pragma unroll
        for (int j2 = 0; j2 < 32; j2++) {
            ulonglong2 ww = w2p[j2];
            acc[2 * j2 + 0] = fma2(h, ww.x, acc[2 * j2 + 0]);
            acc[2 * j2 + 1] = fma2(h, ww.y, acc[2 * j2 + 1]);
        }
    }

    ull mx[8];
#pragma unroll
    for (int k = 0; k < 8; k++) mx[k] = 0ull;
#pragma unroll
    for (int j = 0; j < 64; j++) {
        ull h2 = swish2(mul2(acc[j], c125));
        const ulonglong2* w3p = (const ulonglong2*)&sW3d[j * 8];
#pragma unroll
        for (int k2 = 0; k2 < 4; k2++) {
            ulonglong2 ww = w3p[k2];
            mx[2 * k2 + 0] = fma2(h2, ww.x, mx[2 * k2 + 0]);
            mx[2 * k2 + 1] = fma2(h2, ww.y, mx[2 * k2 + 1]);
        }
    }

    float o0[8], o1[8];
#pragma unroll
    for (int k = 0; k < 8; k++) {
        float x, y; unpack2(mx[k], x, y);
        o0[k] = x * 0.125f;
        o1[k] = y * 0.125f;
    }
    *(float4*)&g_mix[e0 * 8]     = make_float4(o0[0], o0[1], o0[2], o0[3]);
    *(float4*)&g_mix[e0 * 8 + 4] = make_float4(o0[4], o0[5], o0[6], o0[7]);
    if (has1) {
        *(float4*)&g_mix[e1 * 8]     = make_float4(o1[0], o1[1], o1[2], o1[3]);
        *(float4*)&g_mix[e1 * 8 + 4] = make_float4(o1[4], o1[5], o1[6], o1[7]);
    }
}

// ---------------------------------------------------------------------------
// node pre: su/vu (packed record) from current s/v, zero agg
// ---------------------------------------------------------------------------
__global__ void k_node_pre(const float* __restrict__ Wus,
                           const float* __restrict__ Wuv, int nn) {
    int n = blockIdx.x * blockDim.x + threadIdx.x;
    if (n >= nn) return;
    float s = g_s[n];
    float su = s * Wus[0];
    float w00 = Wuv[0], w01 = Wuv[1], w10 = Wuv[2], w11 = Wuv[3];  // [m][k]
    float vu0[3], vu1[3];
#pragma unroll
    for (int c = 0; c < 3; c++) {
        float a = g_v[n * 6 + c], b = g_v[n * 6 + 3 + c];
        vu0[c] = (a * w00 + b * w10) * INV_SQRT2;  // k=0
        vu1[c] = (a * w01 + b * w11) * INV_SQRT2;  // k=1
    }
    *(float4*)&g_vus[n * 8]     = make_float4(vu0[0], vu0[1], vu0[2], su);
    *(float4*)&g_vus[n * 8 + 4] = make_float4(vu1[0], vu1[1], vu1[2], 0.0f);
    float4 z = make_float4(0.f, 0.f, 0.f, 0.f);
#pragma unroll
    for (int i = 0; i < 5; i++) *(float4*)&g_agg[n * 20 + 4 * i] = z;
}

// ---------------------------------------------------------------------------
// per-edge message + vectorized scatter (red.global.add.v4/v2.f32)
// agg layout: [0..2]=msg_s, [3..5]=ve0, [6..8]=ve1, [9..11]=pc0,
//             [12..14]=pc1, [15..17]=pb
// ---------------------------------------------------------------------------
__global__ void k_edge(const int* __restrict__ snd,
                       const int* __restrict__ rcv, int ne) {
    int e = blockIdx.x * blockDim.x + threadIdx.x;
    if (e >= ne) return;
    int s = snd[e], r = rcv[e];
    float4 nh = *(const float4*)&g_nhat[e * 4];
    float nx = nh.x, ny = nh.y, nz = nh.z;
    float4 m0 = *(const float4*)&g_mix[e * 8];      // mix0..3
    float4 m1 = *(const float4*)&g_mix[e * 8 + 4];  // mix4..7

    float4 p0 = *(const float4*)&g_vus[s * 8];      // vu0.xyz, su
    float4 p1 = *(const float4*)&g_vus[s * 8 + 4];  // vu1.xyz
    float se = p0.w;
    float v0x = p0.x, v0y = p0.y, v0z = p0.z;
    float v1x = p1.x, v1y = p1.y, v1z = p1.z;

    float d0 = v0x * nx + v0y * ny + v0z * nz;
    float d1 = v1x * nx + v1y * ny + v1z * nz;

    const float third = 1.0f / 3.0f;
    float c0 = C121_F * m1.y;   // pc0 coef
    float c1 = C121_F * m1.z;   // pc1 coef
    float cb = SQRT3_F * se * m1.w;

    float m_[18];
    m_[0]  = se * m0.x;
    m_[1]  = d0 * m0.y;
    m_[2]  = d1 * m0.z;
    m_[3]  = v0x * m0.w;  m_[4]  = v0y * m0.w;  m_[5]  = v0z * m0.w;
    m_[6]  = v1x * m1.x;  m_[7]  = v1y * m1.x;  m_[8]  = v1z * m1.x;
    m_[9]  = c0 * (d0 * nx - v0x * third);
    m_[10] = c0 * (d0 * ny - v0y * third);
    m_[11] = c0 * (d0 * nz - v0z * third);
    m_[12] = c1 * (d1 * nx - v1x * third);
    m_[13] = c1 * (d1 * ny - v1y * third);
    m_[14] = c1 * (d1 * nz - v1z * third);
    m_[15] = cb * nx;  m_[16] = cb * ny;  m_[17] = cb * nz;

    float* base = &g_agg[r * 20];
#pragma unroll
    for (int q = 0; q < 4; q++) {
        asm volatile("red.global.add.v4.f32 [%0], {%1, %2, %3, %4};"
                     :: "l"(base + 4 * q),
                        "f"(m_[4 * q + 0]), "f"(m_[4 * q + 1]),
                        "f"(m_[4 * q + 2]), "f"(m_[4 * q + 3])
                     : "memory");
    }
    asm volatile("red.global.add.v2.f32 [%0], {%1, %2};"
                 :: "l"(base + 16), "f"(m_[16]), "f"(m_[17]) : "memory");
}

// ---------------------------------------------------------------------------
// node post: downmix agg, residual, gates, update s/v (and write output)
// ---------------------------------------------------------------------------
__global__ void k_node_post(const float* __restrict__ Wss,
                            const float* __restrict__ Wsv,
                            const float* __restrict__ Wds,
                            const float* __restrict__ Wdv,
                            float* __restrict__ out, int write_out, int nn) {
    int n = blockIdx.x * blockDim.x + threadIdx.x;
    if (n >= nn) return;
    float s = g_s[n];
    float v[6];
#pragma unroll
    for (int i = 0; i < 6; i++) v[i] = g_v[n * 6 + i];
    float agg[18];
#pragma unroll
    for (int i = 0; i < 18; i++) agg[i] = g_agg[n * 20 + i];

    float st[3];
#pragma unroll
    for (int k = 0; k < 3; k++) {
        float sd = (agg[0] * Wds[0 * 3 + k] + agg[1] * Wds[1 * 3 + k] +
                    agg[2] * Wds[2 * 3 + k]) * INV_SQRT3;
        st[k] = sd + s * Wss[k];
    }
    float vt[6];
#pragma unroll
    for (int k = 0; k < 2; k++) {
#pragma unroll
        for (int c = 0; c < 3; c++) {
            float vd = 0.0f;
#pragma unroll
            for (int m = 0; m < 5; m++) vd = fmaf(agg[3 + m * 3 + c], Wdv[m * 2 + k], vd);
            vd *= INV_SQRT5;
            float vsc = (v[c] * Wsv[0 * 2 + k] + v[3 + c] * Wsv[1 * 2 + k]) * INV_SQRT2;
            vt[k * 3 + c] = vd + vsc;
        }
    }
    float ns = swishf(st[0]);
    float g1 = swishf(st[1]);
    float g2 = swishf(st[2]);
    g_s[n] = ns;
#pragma unroll
    for (int c = 0; c < 3; c++) {
        float nv0 = vt[c] * g1;
        float nv1 = vt[3 + c] * g2;
        g_v[n * 6 + c]     = nv0;
        g_v[n * 6 + 3 + c] = nv1;
        if (write_out) out[n * 3 + c] = nv0;
    }
}

// ---------------------------------------------------------------------------
// launch
// ---------------------------------------------------------------------------
extern "C" void kernel_launch(void* const* d_in, const int* in_sizes, int n_in,
                              void* d_out, int out_size) {
    const float* pos = (const float*)d_in[0];
    const float* nf  = (const float*)d_in[1];
    const int* snd   = (const int*)d_in[2];
    const int* rcv   = (const int*)d_in[3];
    const float* Wss = (const float*)d_in[4];
    const float* Wsv = (const float*)d_in[5];
    const float* Wus = (const float*)d_in[6];
    const float* Wuv = (const float*)d_in[7];
    const float* W1  = (const float*)d_in[8];
    const float* W2  = (const float*)d_in[9];
    const float* W3  = (const float*)d_in[10];
    const float* Wds = (const float*)d_in[11];
    const float* Wdv = (const float*)d_in[12];
    float* out = (float*)d_out;

    int ne = in_sizes[2];
    int nn = in_sizes[0] / 3;

    int nb_n = (nn + 255) / 256;
    int nb_e = (ne + 255) / 256;
    int nb_m = (ne + 255) / 256;  // 2 edges/thread, 128 threads/block

    k_init<<<nb_n, 256>>>(nf, nn);
    k_geom<<<nb_e, 256>>>(pos, snd, rcv, ne);

    for (int l = 0; l < 3; l++) {
        k_node_pre<<<nb_n, 256>>>(Wus + l * 1, Wuv + l * 4, nn);
        k_mix<<<nb_m, 128>>>(W1 + l * 512, W2 + l * 4096, W3 + l * 512, ne);
        k_edge<<<nb_e, 256>>>(snd, rcv, ne);
        k_node_post<<<nb_n, 256>>>(Wss + l * 3, Wsv + l * 4, Wds + l * 9,
                                   Wdv + l * 10, out, (l == 2) ? 1 : 0, nn);
    }
}

// round 4
// speedup vs baseline: 1.3465x; 1.3465x over previous
#include <cuda_runtime.h>
#include <math.h>

typedef unsigned long long ull;

#define NN_MAX 50000
#define NE_MAX 1000000

// ---- device-global scratch (no allocations allowed) ----
__device__ float g_s[NN_MAX];            // scalar feature per node
__device__ float g_v[NN_MAX * 6];        // vector features (2,3) per node
__device__ float g_vus[NN_MAX * 8];      // packed: [vu0.xyz, su, vu1.xyz, pad]
__device__ float g_agg[NN_MAX * 20];     // 18 used, padded to 20 (16B aligned)
__device__ float g_nhat[NE_MAX * 4];     // padded to float4
__device__ float g_radial[NE_MAX * 8];
__device__ float g_mix[NE_MAX * 8];

#define INV_SQRT2 0.70710678118654752f
#define INV_SQRT3 0.57735026918962576f
#define INV_SQRT5 0.44721359549995794f
#define INV_SQRT8 0.35355339059327376f
#define SQRT2_F   1.4142135623730951f
#define C121_F    2.1213203435596424f
#define SQRT3_F   1.7320508075688772f

__device__ __forceinline__ float swishf(float x) {
    return x / (1.0f + __expf(-x));
}

// ---- packed f32x2 helpers (SASS FFMA2 path, PTX-only) ----
__device__ __forceinline__ ull pack2(float x, float y) {
    ull r; asm("mov.b64 %0, {%1, %2};" : "=l"(r) : "f"(x), "f"(y)); return r;
}
__device__ __forceinline__ void unpack2(ull v, float& x, float& y) {
    asm("mov.b64 {%0, %1}, %2;" : "=f"(x), "=f"(y) : "l"(v));
}
__device__ __forceinline__ ull fma2(ull a, ull b, ull c) {
    ull d; asm("fma.rn.f32x2 %0, %1, %2, %3;" : "=l"(d) : "l"(a), "l"(b), "l"(c)); return d;
}

// ---------------------------------------------------------------------------
// init node state from node_features
// ---------------------------------------------------------------------------
__global__ void k_init(const float* __restrict__ nf, int nn) {
    int n = blockIdx.x * blockDim.x + threadIdx.x;
    if (n >= nn) return;
    g_s[n] = nf[n * 7];
#pragma unroll
    for (int i = 0; i < 6; i++) g_v[n * 6 + i] = nf[n * 7 + 1 + i];
}

// ---------------------------------------------------------------------------
// per-edge geometry: nhat (padded float4) + radial basis (8 features)
// ---------------------------------------------------------------------------
__global__ void k_geom(const float* __restrict__ pos,
                       const int* __restrict__ snd,
                       const int* __restrict__ rcv, int ne) {
    int e = blockIdx.x * blockDim.x + threadIdx.x;
    if (e >= ne) return;
    int s = snd[e], r = rcv[e];
    float vx = pos[r * 3 + 0] - pos[s * 3 + 0];
    float vy = pos[r * 3 + 1] - pos[s * 3 + 1];
    float vz = pos[r * 3 + 2] - pos[s * 3 + 2];
    float len = sqrtf(vx * vx + vy * vy + vz * vz);
    float inv = (len == 0.0f) ? 1.0f : (1.0f / len);
    *(float4*)&g_nhat[e * 4] = make_float4(vx * inv, vy * inv, vz * inv, 0.0f);

    float env = 0.0f;
    if (len < 1.0f) {
        float x = len;
        float x2 = x * x, x3 = x2 * x;
        float x6 = x3 * x3, x7 = x6 * x, x8 = x7 * x;
        env = 1.0f - 28.0f * x6 + 48.0f * x7 - 21.0f * x8;
    }
    float coef = (len == 0.0f) ? 0.0f : (SQRT2_F * env * inv);

    float s1, c1;
    sincospif(len, &s1, &c1);
    float out[8];
    float sm1 = 0.0f, sk = s1;
#pragma unroll
    for (int k = 0; k < 8; k++) {
        out[k] = sk * coef;
        float nx = 2.0f * c1 * sk - sm1;
        sm1 = sk; sk = nx;
    }
    *(float4*)&g_radial[e * 8]     = make_float4(out[0], out[1], out[2], out[3]);
    *(float4*)&g_radial[e * 8 + 4] = make_float4(out[4], out[5], out[6], out[7]);
}

// ---------------------------------------------------------------------------
// radial MLP, 1 edge/thread, packed along the j (channel) dimension (FFMA2).
// acc2[j2] = (acc[2j], acc[2j+1]); weight pairs are contiguous in row-major
// layout so no duplication needed. h_i broadcast-packed as (h,h).
// ---------------------------------------------------------------------------
__global__ __launch_bounds__(128) void k_mix(const float* __restrict__ W1,
                                             const float* __restrict__ W2,
                                             const float* __restrict__ W3,
                                             int ne) {
    __shared__ __align__(16) float sW1t[64 * 8];   // transposed: [i][m]
    __shared__ __align__(16) float sW2[64 * 64];   // [i][j] row-major
    __shared__ __align__(16) float sW3[64 * 8];    // [j][k] row-major
    for (int i = threadIdx.x; i < 512; i += 128) {
        int m = i & 7, ii = i >> 3;
        sW1t[i] = W1[m * 64 + ii];   // sW1t[ii*8+m] = W1[m][ii]
        sW3[i]  = W3[i];
    }
    for (int i = threadIdx.x; i < 4096; i += 128) sW2[i] = W2[i];
    __syncthreads();

    int e = blockIdx.x * blockDim.x + threadIdx.x;
    if (e >= ne) return;

    float4 ra = *(const float4*)&g_radial[e * 8];
    float4 rb = *(const float4*)&g_radial[e * 8 + 4];

    ull acc2[32];
#pragma unroll
    for (int j = 0; j < 32; j++) acc2[j] = 0ull;

#pragma unroll 4
    for (int i = 0; i < 64; i++) {
        // h_i = swish(<r, W1[:,i]> / sqrt(8))
        const float4* w1p = (const float4*)&sW1t[i * 8];
        float4 wa = w1p[0], wb = w1p[1];
        float h = ra.x * wa.x;
        h = fmaf(ra.y, wa.y, h);
        h = fmaf(ra.z, wa.z, h);
        h = fmaf(ra.w, wa.w, h);
        h = fmaf(rb.x, wb.x, h);
        h = fmaf(rb.y, wb.y, h);
        h = fmaf(rb.z, wb.z, h);
        h = fmaf(rb.w, wb.w, h);
        h = swishf(h * INV_SQRT8);
        ull hp = pack2(h, h);
        // sweep row i of W2: 16 LDS.128 + 32 FFMA2
        const ulonglong2* w2p = (const ulonglong2*)&sW2[i * 64];
#pragma unroll
        for (int q = 0; q < 16; q++) {
            ulonglong2 ww = w2p[q];
            acc2[2 * q + 0] = fma2(hp, ww.x, acc2[2 * q + 0]);
            acc2[2 * q + 1] = fma2(hp, ww.y, acc2[2 * q + 1]);
        }
    }

    ull mx2[4];
#pragma unroll
    for (int k = 0; k < 4; k++) mx2[k] = 0ull;
#pragma unroll
    for (int j2 = 0; j2 < 32; j2++) {
        float a0, a1;
        unpack2(acc2[j2], a0, a1);
        float h20 = swishf(a0 * 0.125f);
        float h21 = swishf(a1 * 0.125f);
        ull hp0 = pack2(h20, h20);
        ull hp1 = pack2(h21, h21);
        const ulonglong2* w3a = (const ulonglong2*)&sW3[(2 * j2) * 8];
        ulonglong2 wa = w3a[0], wb = w3a[1];
        mx2[0] = fma2(hp0, wa.x, mx2[0]);
        mx2[1] = fma2(hp0, wa.y, mx2[1]);
        mx2[2] = fma2(hp0, wb.x, mx2[2]);
        mx2[3] = fma2(hp0, wb.y, mx2[3]);
        const ulonglong2* w3b = (const ulonglong2*)&sW3[(2 * j2 + 1) * 8];
        ulonglong2 wc = w3b[0], wd = w3b[1];
        mx2[0] = fma2(hp1, wc.x, mx2[0]);
        mx2[1] = fma2(hp1, wc.y, mx2[1]);
        mx2[2] = fma2(hp1, wd.x, mx2[2]);
        mx2[3] = fma2(hp1, wd.y, mx2[3]);
    }

    float o[8];
#pragma unroll
    for (int k = 0; k < 4; k++) {
        float x, y;
        unpack2(mx2[k], x, y);
        o[2 * k]     = x * 0.125f;
        o[2 * k + 1] = y * 0.125f;
    }
    *(float4*)&g_mix[e * 8]     = make_float4(o[0], o[1], o[2], o[3]);
    *(float4*)&g_mix[e * 8 + 4] = make_float4(o[4], o[5], o[6], o[7]);
}

// ---------------------------------------------------------------------------
// node pre: su/vu (packed record) from current s/v, zero agg
// ---------------------------------------------------------------------------
__global__ void k_node_pre(const float* __restrict__ Wus,
                           const float* __restrict__ Wuv, int nn) {
    int n = blockIdx.x * blockDim.x + threadIdx.x;
    if (n >= nn) return;
    float s = g_s[n];
    float su = s * Wus[0];
    float w00 = Wuv[0], w01 = Wuv[1], w10 = Wuv[2], w11 = Wuv[3];  // [m][k]
    float vu0[3], vu1[3];
#pragma unroll
    for (int c = 0; c < 3; c++) {
        float a = g_v[n * 6 + c], b = g_v[n * 6 + 3 + c];
        vu0[c] = (a * w00 + b * w10) * INV_SQRT2;  // k=0
        vu1[c] = (a * w01 + b * w11) * INV_SQRT2;  // k=1
    }
    *(float4*)&g_vus[n * 8]     = make_float4(vu0[0], vu0[1], vu0[2], su);
    *(float4*)&g_vus[n * 8 + 4] = make_float4(vu1[0], vu1[1], vu1[2], 0.0f);
    float4 z = make_float4(0.f, 0.f, 0.f, 0.f);
#pragma unroll
    for (int i = 0; i < 5; i++) *(float4*)&g_agg[n * 20 + 4 * i] = z;
}

// ---------------------------------------------------------------------------
// per-edge message + vectorized scatter (red.global.add.v4/v2.f32)
// agg layout: [0..2]=msg_s, [3..5]=ve0, [6..8]=ve1, [9..11]=pc0,
//             [12..14]=pc1, [15..17]=pb
// ---------------------------------------------------------------------------
__global__ void k_edge(const int* __restrict__ snd,
                       const int* __restrict__ rcv, int ne) {
    int e = blockIdx.x * blockDim.x + threadIdx.x;
    if (e >= ne) return;
    int s = snd[e], r = rcv[e];
    float4 nh = *(const float4*)&g_nhat[e * 4];
    float nx = nh.x, ny = nh.y, nz = nh.z;
    float4 m0 = *(const float4*)&g_mix[e * 8];      // mix0..3
    float4 m1 = *(const float4*)&g_mix[e * 8 + 4];  // mix4..7

    float4 p0 = *(const float4*)&g_vus[s * 8];      // vu0.xyz, su
    float4 p1 = *(const float4*)&g_vus[s * 8 + 4];  // vu1.xyz
    float se = p0.w;
    float v0x = p0.x, v0y = p0.y, v0z = p0.z;
    float v1x = p1.x, v1y = p1.y, v1z = p1.z;

    float d0 = v0x * nx + v0y * ny + v0z * nz;
    float d1 = v1x * nx + v1y * ny + v1z * nz;

    const float third = 1.0f / 3.0f;
    float c0 = C121_F * m1.y;   // pc0 coef
    float c1 = C121_F * m1.z;   // pc1 coef
    float cb = SQRT3_F * se * m1.w;

    float m_[18];
    m_[0]  = se * m0.x;
    m_[1]  = d0 * m0.y;
    m_[2]  = d1 * m0.z;
    m_[3]  = v0x * m0.w;  m_[4]  = v0y * m0.w;  m_[5]  = v0z * m0.w;
    m_[6]  = v1x * m1.x;  m_[7]  = v1y * m1.x;  m_[8]  = v1z * m1.x;
    m_[9]  = c0 * (d0 * nx - v0x * third);
    m_[10] = c0 * (d0 * ny - v0y * third);
    m_[11] = c0 * (d0 * nz - v0z * third);
    m_[12] = c1 * (d1 * nx - v1x * third);
    m_[13] = c1 * (d1 * ny - v1y * third);
    m_[14] = c1 * (d1 * nz - v1z * third);
    m_[15] = cb * nx;  m_[16] = cb * ny;  m_[17] = cb * nz;

    float* base = &g_agg[r * 20];
#pragma unroll
    for (int q = 0; q < 4; q++) {
        asm volatile("red.global.add.v4.f32 [%0], {%1, %2, %3, %4};"
                     :: "l"(base + 4 * q),
                        "f"(m_[4 * q + 0]), "f"(m_[4 * q + 1]),
                        "f"(m_[4 * q + 2]), "f"(m_[4 * q + 3])
                     : "memory");
    }
    asm volatile("red.global.add.v2.f32 [%0], {%1, %2};"
                 :: "l"(base + 16), "f"(m_[16]), "f"(m_[17]) : "memory");
}

// ---------------------------------------------------------------------------
// node post: downmix agg, residual, gates, update s/v (and write output)
// ---------------------------------------------------------------------------
__global__ void k_node_post(const float* __restrict__ Wss,
                            const float* __restrict__ Wsv,
                            const float* __restrict__ Wds,
                            const float* __restrict__ Wdv,
                            float* __restrict__ out, int write_out, int nn) {
    int n = blockIdx.x * blockDim.x + threadIdx.x;
    if (n >= nn) return;
    float s = g_s[n];
    float v[6];
#pragma unroll
    for (int i = 0; i < 6; i++) v[i] = g_v[n * 6 + i];
    float agg[18];
#pragma unroll
    for (int i = 0; i < 18; i++) agg[i] = g_agg[n * 20 + i];

    float st[3];
#pragma unroll
    for (int k = 0; k < 3; k++) {
        float sd = (agg[0] * Wds[0 * 3 + k] + agg[1] * Wds[1 * 3 + k] +
                    agg[2] * Wds[2 * 3 + k]) * INV_SQRT3;
        st[k] = sd + s * Wss[k];
    }
    float vt[6];
#pragma unroll
    for (int k = 0; k < 2; k++) {
#pragma unroll
        for (int c = 0; c < 3; c++) {
            float vd = 0.0f;
#pragma unroll
            for (int m = 0; m < 5; m++) vd = fmaf(agg[3 + m * 3 + c], Wdv[m * 2 + k], vd);
            vd *= INV_SQRT5;
            float vsc = (v[c] * Wsv[0 * 2 + k] + v[3 + c] * Wsv[1 * 2 + k]) * INV_SQRT2;
            vt[k * 3 + c] = vd + vsc;
        }
    }
    float ns = swishf(st[0]);
    float g1 = swishf(st[1]);
    float g2 = swishf(st[2]);
    g_s[n] = ns;
#pragma unroll
    for (int c = 0; c < 3; c++) {
        float nv0 = vt[c] * g1;
        float nv1 = vt[3 + c] * g2;
        g_v[n * 6 + c]     = nv0;
        g_v[n * 6 + 3 + c] = nv1;
        if (write_out) out[n * 3 + c] = nv0;
    }
}

// ---------------------------------------------------------------------------
// launch
// ---------------------------------------------------------------------------
extern "C" void kernel_launch(void* const* d_in, const int* in_sizes, int n_in,
                              void* d_out, int out_size) {
    const float* pos = (const float*)d_in[0];
    const float* nf  = (const float*)d_in[1];
    const int* snd   = (const int*)d_in[2];
    const int* rcv   = (const int*)d_in[3];
    const float* Wss = (const float*)d_in[4];
    const float* Wsv = (const float*)d_in[5];
    const float* Wus = (const float*)d_in[6];
    const float* Wuv = (const float*)d_in[7];
    const float* W1  = (const float*)d_in[8];
    const float* W2  = (const float*)d_in[9];
    const float* W3  = (const float*)d_in[10];
    const float* Wds = (const float*)d_in[11];
    const float* Wdv = (const float*)d_in[12];
    float* out = (float*)d_out;

    int ne = in_sizes[2];
    int nn = in_sizes[0] / 3;

    int nb_n = (nn + 255) / 256;
    int nb_e = (ne + 255) / 256;
    int nb_m = (ne + 127) / 128;

    k_init<<<nb_n, 256>>>(nf, nn);
    k_geom<<<nb_e, 256>>>(pos, snd, rcv, ne);

    for (int l = 0; l < 3; l++) {
        k_node_pre<<<nb_n, 256>>>(Wus + l * 1, Wuv + l * 4, nn);
        k_mix<<<nb_m, 128>>>(W1 + l * 512, W2 + l * 4096, W3 + l * 512, ne);
        k_edge<<<nb_e, 256>>>(snd, rcv, ne);
        k_node_post<<<nb_n, 256>>>(Wss + l * 3, Wsv + l * 4, Wds + l * 9,
                                   Wdv + l * 10, out, (l == 2) ? 1 : 0, nn);
    }
}

// round 6
// speedup vs baseline: 1.4913x; 1.1076x over previous
#include <cuda_runtime.h>
#include <math.h>

typedef unsigned long long ull;

#define NN_MAX 50000
#define NE_MAX 1000000

// ---- device-global scratch (no allocations allowed) ----
__device__ float g_s[NN_MAX];            // scalar feature per node
__device__ float g_v[NN_MAX * 6];        // vector features (2,3) per node
__device__ float g_vus[NN_MAX * 8];      // packed: [vu0.xyz, su, vu1.xyz, pad]
__device__ float g_agg[NN_MAX * 20];     // 18 used, padded to 20 (16B aligned)
__device__ float g_nhat[NE_MAX * 4];     // padded to float4
__device__ float g_radial[NE_MAX * 8];
__device__ float g_mix[NE_MAX * 8];

#define INV_SQRT2 0.70710678118654752f
#define INV_SQRT3 0.57735026918962576f
#define INV_SQRT5 0.44721359549995794f
#define INV_SQRT8 0.35355339059327376f
#define SQRT2_F   1.4142135623730951f
#define C121_F    2.1213203435596424f
#define SQRT3_F   1.7320508075688772f

__device__ __forceinline__ float swishf(float x) {
    return x / (1.0f + __expf(-x));
}

// ---- packed f32x2 helpers (SASS FFMA2 path, PTX-only) ----
__device__ __forceinline__ ull pack2(float x, float y) {
    ull r; asm("mov.b64 %0, {%1, %2};" : "=l"(r) : "f"(x), "f"(y)); return r;
}
__device__ __forceinline__ void unpack2(ull v, float& x, float& y) {
    asm("mov.b64 {%0, %1}, %2;" : "=f"(x), "=f"(y) : "l"(v));
}
__device__ __forceinline__ ull fma2(ull a, ull b, ull c) {
    ull d; asm("fma.rn.f32x2 %0, %1, %2, %3;" : "=l"(d) : "l"(a), "l"(b), "l"(c)); return d;
}
__device__ __forceinline__ ull add2(ull a, ull b) {
    ull d; asm("add.rn.f32x2 %0, %1, %2;" : "=l"(d) : "l"(a), "l"(b)); return d;
}
__device__ __forceinline__ ull mul2(ull a, ull b) {
    ull d; asm("mul.rn.f32x2 %0, %1, %2;" : "=l"(d) : "l"(a), "l"(b)); return d;
}

// ---------------------------------------------------------------------------
// init node state from node_features
// ---------------------------------------------------------------------------
__global__ void k_init(const float* __restrict__ nf, int nn) {
    int n = blockIdx.x * blockDim.x + threadIdx.x;
    if (n >= nn) return;
    g_s[n] = nf[n * 7];
#pragma unroll
    for (int i = 0; i < 6; i++) g_v[n * 6 + i] = nf[n * 7 + 1 + i];
}

// ---------------------------------------------------------------------------
// per-edge geometry: nhat (padded float4) + radial basis (8 features)
// ---------------------------------------------------------------------------
__global__ void k_geom(const float* __restrict__ pos,
                       const int* __restrict__ snd,
                       const int* __restrict__ rcv, int ne) {
    int e = blockIdx.x * blockDim.x + threadIdx.x;
    if (e >= ne) return;
    int s = snd[e], r = rcv[e];
    float vx = pos[r * 3 + 0] - pos[s * 3 + 0];
    float vy = pos[r * 3 + 1] - pos[s * 3 + 1];
    float vz = pos[r * 3 + 2] - pos[s * 3 + 2];
    float len = sqrtf(vx * vx + vy * vy + vz * vz);
    float inv = (len == 0.0f) ? 1.0f : (1.0f / len);
    *(float4*)&g_nhat[e * 4] = make_float4(vx * inv, vy * inv, vz * inv, 0.0f);

    float env = 0.0f;
    if (len < 1.0f) {
        float x = len;
        float x2 = x * x, x3 = x2 * x;
        float x6 = x3 * x3, x7 = x6 * x, x8 = x7 * x;
        env = 1.0f - 28.0f * x6 + 48.0f * x7 - 21.0f * x8;
    }
    float coef = (len == 0.0f) ? 0.0f : (SQRT2_F * env * inv);

    float s1, c1;
    sincospif(len, &s1, &c1);
    float out[8];
    float sm1 = 0.0f, sk = s1;
#pragma unroll
    for (int k = 0; k < 8; k++) {
        out[k] = sk * coef;
        float nx = 2.0f * c1 * sk - sm1;
        sm1 = sk; sk = nx;
    }
    *(float4*)&g_radial[e * 8]     = make_float4(out[0], out[1], out[2], out[3]);
    *(float4*)&g_radial[e * 8 + 4] = make_float4(out[4], out[5], out[6], out[7]);
}

// ---------------------------------------------------------------------------
// radial MLP: lane-pair cooperative, FFMA2 j-packed.
// Lanes (t, t^1) each own one edge; each accumulates BOTH edges over half the
// channels (alternating 16B chunks: chunk = 2q + parity), so one broadcast
// LDS.128 of W2 feeds 4 FFMA2. h exchanged via shfl.xor(1); W3 partials
// exchanged at the end via 64-bit shfl + add.rn.f32x2.
// ---------------------------------------------------------------------------
__global__ __launch_bounds__(128) void k_mix(const float* __restrict__ W1,
                                             const float* __restrict__ W2,
                                             const float* __restrict__ W3,
                                             int ne) {
    __shared__ __align__(16) float sW1t[64 * 8];   // transposed: [i][m]
    __shared__ __align__(16) float sW2[64 * 64];   // [i][j] row-major
    __shared__ __align__(16) float sW3[64 * 8];    // [j][k] row-major
    for (int i = threadIdx.x; i < 512; i += 128) {
        int m = i & 7, ii = i >> 3;
        sW1t[i] = W1[m * 64 + ii];   // sW1t[ii*8+m] = W1[m][ii]
        sW3[i]  = W3[i];
    }
    for (int i = threadIdx.x; i < 4096; i += 128) sW2[i] = W2[i];
    __syncthreads();

    int tid = threadIdx.x;
    int e = blockIdx.x * 128 + tid;
    if (e >= ne) e = ne - 1;          // clamp: keep warp converged for shfl
    int p = tid & 1;                  // lane parity -> channel-chunk set

    float4 ra = *(const float4*)&g_radial[e * 8];
    float4 rb = *(const float4*)&g_radial[e * 8 + 4];
    ull r01 = pack2(ra.x, ra.y), r23 = pack2(ra.z, ra.w);
    ull r45 = pack2(rb.x, rb.y), r67 = pack2(rb.z, rb.w);

    ull acc_own[16], acc_oth[16];
#pragma unroll
    for (int q = 0; q < 16; q++) { acc_own[q] = 0ull; acc_oth[q] = 0ull; }

    const float* w2p0 = &sW2[p * 4];   // parity chunk offset (16B)

#pragma unroll 4
    for (int i = 0; i < 64; i++) {
        // h_i(own edge) = swish(<r, W1[:,i]>/sqrt(8))  via FFMA2 + h-add
        const ulonglong2* w1p = (const ulonglong2*)&sW1t[i * 8];
        ulonglong2 wa = w1p[0], wb = w1p[1];
        ull ha = fma2(r01, wa.x, 0ull);
        ha = fma2(r23, wa.y, ha);
        ha = fma2(r45, wb.x, ha);
        ha = fma2(r67, wb.y, ha);
        float hx, hy; unpack2(ha, hx, hy);
        float h = swishf((hx + hy) * INV_SQRT8);
        float ho = __shfl_xor_sync(0xFFFFFFFFu, h, 1);  // partner's h
        ull hp = pack2(h, h);
        ull hq = pack2(ho, ho);
        // sweep thread's 8 chunks of row i: 8 LDS.128, 32 FFMA2
        const float* row = w2p0 + i * 64;
#pragma unroll
        for (int q = 0; q < 8; q++) {
            ulonglong2 ww = *(const ulonglong2*)&row[q * 8];
            acc_own[2 * q + 0] = fma2(hp, ww.x, acc_own[2 * q + 0]);
            acc_own[2 * q + 1] = fma2(hp, ww.y, acc_own[2 * q + 1]);
            acc_oth[2 * q + 0] = fma2(hq, ww.x, acc_oth[2 * q + 0]);
            acc_oth[2 * q + 1] = fma2(hq, ww.y, acc_oth[2 * q + 1]);
        }
    }

    // W3 stage over thread's 32 channels (chunks 2q+p), both edges
    ull mxo[4] = {0ull, 0ull, 0ull, 0ull};   // partial mix, own edge
    ull mxp[4] = {0ull, 0ull, 0ull, 0ull};   // partial mix, partner edge
#pragma unroll
    for (int q = 0; q < 8; q++) {
        int jbase = 4 * (2 * q + p);
#pragma unroll
        for (int t = 0; t < 2; t++) {
            float a0, a1, b0, b1;
            unpack2(acc_own[2 * q + t], a0, a1);
            unpack2(acc_oth[2 * q + t], b0, b1);
            int j0 = jbase + 2 * t;
            // channel j0
            {
                float h2o = swishf(a0 * 0.125f);
                float h2p = swishf(b0 * 0.125f);
                const ulonglong2* w3 = (const ulonglong2*)&sW3[j0 * 8];
                ulonglong2 w0 = w3[0], w1 = w3[1];
                ull go = pack2(h2o, h2o), gp = pack2(h2p, h2p);
                mxo[0] = fma2(go, w0.x, mxo[0]);
                mxo[1] = fma2(go, w0.y, mxo[1]);
                mxo[2] = fma2(go, w1.x, mxo[2]);
                mxo[3] = fma2(go, w1.y, mxo[3]);
                mxp[0] = fma2(gp, w0.x, mxp[0]);
                mxp[1] = fma2(gp, w0.y, mxp[1]);
                mxp[2] = fma2(gp, w1.x, mxp[2]);
                mxp[3] = fma2(gp, w1.y, mxp[3]);
            }
            // channel j0+1
            {
                float h2o = swishf(a1 * 0.125f);
                float h2p = swishf(b1 * 0.125f);
                const ulonglong2* w3 = (const ulonglong2*)&sW3[(j0 + 1) * 8];
                ulonglong2 w0 = w3[0], w1 = w3[1];
                ull go = pack2(h2o, h2o), gp = pack2(h2p, h2p);
                mxo[0] = fma2(go, w0.x, mxo[0]);
                mxo[1] = fma2(go, w0.y, mxo[1]);
                mxo[2] = fma2(go, w1.x, mxo[2]);
                mxo[3] = fma2(go, w1.y, mxo[3]);
                mxp[0] = fma2(gp, w0.x, mxp[0]);
                mxp[1] = fma2(gp, w0.y, mxp[1]);
                mxp[2] = fma2(gp, w1.x, mxp[2]);
                mxp[3] = fma2(gp, w1.y, mxp[3]);
            }
        }
    }

    // exchange partner partials and finalize
    const ull c125 = pack2(0.125f, 0.125f);
    float o[8];
#pragma unroll
    for (int k = 0; k < 4; k++) {
        ull rec = __shfl_xor_sync(0xFFFFFFFFu, mxp[k], 1);
        ull tot = mul2(add2(mxo[k], rec), c125);
        unpack2(tot, o[2 * k], o[2 * k + 1]);
    }
    *(float4*)&g_mix[e * 8]     = make_float4(o[0], o[1], o[2], o[3]);
    *(float4*)&g_mix[e * 8 + 4] = make_float4(o[4], o[5], o[6], o[7]);
}

// ---------------------------------------------------------------------------
// node pre: su/vu (packed record) from current s/v, zero agg
// ---------------------------------------------------------------------------
__global__ void k_node_pre(const float* __restrict__ Wus,
                           const float* __restrict__ Wuv, int nn) {
    int n = blockIdx.x * blockDim.x + threadIdx.x;
    if (n >= nn) return;
    float s = g_s[n];
    float su = s * Wus[0];
    float w00 = Wuv[0], w01 = Wuv[1], w10 = Wuv[2], w11 = Wuv[3];  // [m][k]
    float vu0[3], vu1[3];
#pragma unroll
    for (int c = 0; c < 3; c++) {
        float a = g_v[n * 6 + c], b = g_v[n * 6 + 3 + c];
        vu0[c] = (a * w00 + b * w10) * INV_SQRT2;  // k=0
        vu1[c] = (a * w01 + b * w11) * INV_SQRT2;  // k=1
    }
    *(float4*)&g_vus[n * 8]     = make_float4(vu0[0], vu0[1], vu0[2], su);
    *(float4*)&g_vus[n * 8 + 4] = make_float4(vu1[0], vu1[1], vu1[2], 0.0f);
    float4 z = make_float4(0.f, 0.f, 0.f, 0.f);
#pragma unroll
    for (int i = 0; i < 5; i++) *(float4*)&g_agg[n * 20 + 4 * i] = z;
}

// ---------------------------------------------------------------------------
// per-edge message + vectorized scatter (red.global.add.v4/v2.f32)
// agg layout: [0..2]=msg_s, [3..5]=ve0, [6..8]=ve1, [9..11]=pc0,
//             [12..14]=pc1, [15..17]=pb
// ---------------------------------------------------------------------------
__global__ void k_edge(const int* __restrict__ snd,
                       const int* __restrict__ rcv, int ne) {
    int e = blockIdx.x * blockDim.x + threadIdx.x;
    if (e >= ne) return;
    int s = snd[e], r = rcv[e];
    float4 nh = *(const float4*)&g_nhat[e * 4];
    float nx = nh.x, ny = nh.y, nz = nh.z;
    float4 m0 = *(const float4*)&g_mix[e * 8];      // mix0..3
    float4 m1 = *(const float4*)&g_mix[e * 8 + 4];  // mix4..7

    float4 p0 = *(const float4*)&g_vus[s * 8];      // vu0.xyz, su
    float4 p1 = *(const float4*)&g_vus[s * 8 + 4];  // vu1.xyz
    float se = p0.w;
    float v0x = p0.x, v0y = p0.y, v0z = p0.z;
    float v1x = p1.x, v1y = p1.y, v1z = p1.z;

    float d0 = v0x * nx + v0y * ny + v0z * nz;
    float d1 = v1x * nx + v1y * ny + v1z * nz;

    const float third = 1.0f / 3.0f;
    float c0 = C121_F * m1.y;   // pc0 coef
    float c1 = C121_F * m1.z;   // pc1 coef
    float cb = SQRT3_F * se * m1.w;

    float m_[18];
    m_[0]  = se * m0.x;
    m_[1]  = d0 * m0.y;
    m_[2]  = d1 * m0.z;
    m_[3]  = v0x * m0.w;  m_[4]  = v0y * m0.w;  m_[5]  = v0z * m0.w;
    m_[6]  = v1x * m1.x;  m_[7]  = v1y * m1.x;  m_[8]  = v1z * m1.x;
    m_[9]  = c0 * (d0 * nx - v0x * third);
    m_[10] = c0 * (d0 * ny - v0y * third);
    m_[11] = c0 * (d0 * nz - v0z * third);
    m_[12] = c1 * (d1 * nx - v1x * third);
    m_[13] = c1 * (d1 * ny - v1y * third);
    m_[14] = c1 * (d1 * nz - v1z * third);
    m_[15] = cb * nx;  m_[16] = cb * ny;  m_[17] = cb * nz;

    float* base = &g_agg[r * 20];
#pragma unroll
    for (int q = 0; q < 4; q++) {
        asm volatile("red.global.add.v4.f32 [%0], {%1, %2, %3, %4};"
                     :: "l"(base + 4 * q),
                        "f"(m_[4 * q + 0]), "f"(m_[4 * q + 1]),
                        "f"(m_[4 * q + 2]), "f"(m_[4 * q + 3])
                     : "memory");
    }
    asm volatile("red.global.add.v2.f32 [%0], {%1, %2};"
                 :: "l"(base + 16), "f"(m_[16]), "f"(m_[17]) : "memory");
}

// ---------------------------------------------------------------------------
// node post: downmix agg, residual, gates, update s/v (and write output)
// ---------------------------------------------------------------------------
__global__ void k_node_post(const float* __restrict__ Wss,
                            const float* __restrict__ Wsv,
                            const float* __restrict__ Wds,
                            const float* __restrict__ Wdv,
                            float* __restrict__ out, int write_out, int nn) {
    int n = blockIdx.x * blockDim.x + threadIdx.x;
    if (n >= nn) return;
    float s = g_s[n];
    float v[6];
#pragma unroll
    for (int i = 0; i < 6; i++) v[i] = g_v[n * 6 + i];
    float agg[18];
#pragma unroll
    for (int i = 0; i < 18; i++) agg[i] = g_agg[n * 20 + i];

    float st[3];
#pragma unroll
    for (int k = 0; k < 3; k++) {
        float sd = (agg[0] * Wds[0 * 3 + k] + agg[1] * Wds[1 * 3 + k] +
                    agg[2] * Wds[2 * 3 + k]) * INV_SQRT3;
        st[k] = sd + s * Wss[k];
    }
    float vt[6];
#pragma unroll
    for (int k = 0; k < 2; k++) {
#pragma unroll
        for (int c = 0; c < 3; c++) {
            float vd = 0.0f;
#pragma unroll
            for (int m = 0; m < 5; m++) vd = fmaf(agg[3 + m * 3 + c], Wdv[m * 2 + k], vd);
            vd *= INV_SQRT5;
            float vsc = (v[c] * Wsv[0 * 2 + k] + v[3 + c] * Wsv[1 * 2 + k]) * INV_SQRT2;
            vt[k * 3 + c] = vd + vsc;
        }
    }
    float ns = swishf(st[0]);
    float g1 = swishf(st[1]);
    float g2 = swishf(st[2]);
    g_s[n] = ns;
#pragma unroll
    for (int c = 0; c < 3; c++) {
        float nv0 = vt[c] * g1;
        float nv1 = vt[3 + c] * g2;
        g_v[n * 6 + c]     = nv0;
        g_v[n * 6 + 3 + c] = nv1;
        if (write_out) out[n * 3 + c] = nv0;
    }
}

// ---------------------------------------------------------------------------
// launch
// ---------------------------------------------------------------------------
extern "C" void kernel_launch(void* const* d_in, const int* in_sizes, int n_in,
                              void* d_out, int out_size) {
    const float* pos = (const float*)d_in[0];
    const float* nf  = (const float*)d_in[1];
    const int* snd   = (const int*)d_in[2];
    const int* rcv   = (const int*)d_in[3];
    const float* Wss = (const float*)d_in[4];
    const float* Wsv = (const float*)d_in[5];
    const float* Wus = (const float*)d_in[6];
    const float* Wuv = (const float*)d_in[7];
    const float* W1  = (const float*)d_in[8];
    const float* W2  = (const float*)d_in[9];
    const float* W3  = (const float*)d_in[10];
    const float* Wds = (const float*)d_in[11];
    const float* Wdv = (const float*)d_in[12];
    float* out = (float*)d_out;

    int ne = in_sizes[2];
    int nn = in_sizes[0] / 3;

    int nb_n = (nn + 255) / 256;
    int nb_e = (ne + 255) / 256;
    int nb_m = (ne + 127) / 128;

    k_init<<<nb_n, 256>>>(nf, nn);
    k_geom<<<nb_e, 256>>>(pos, snd, rcv, ne);

    for (int l = 0; l < 3; l++) {
        k_node_pre<<<nb_n, 256>>>(Wus + l * 1, Wuv + l * 4, nn);
        k_mix<<<nb_m, 128>>>(W1 + l * 512, W2 + l * 4096, W3 + l * 512, ne);
        k_edge<<<nb_e, 256>>>(snd, rcv, ne);
        k_node_post<<<nb_n, 256>>>(Wss + l * 3, Wsv + l * 4, Wds + l * 9,
                                   Wdv + l * 10, out, (l == 2) ? 1 : 0, nn);
    }
}

// round 8
// speedup vs baseline: 1.7543x; 1.1763x over previous
#include <cuda_runtime.h>
#include <math.h>
#include <stdint.h>

typedef unsigned long long ull;

#define NN_MAX 50000
#define NE_MAX 1000000

// ---- device-global scratch (no allocations allowed) ----
__device__ float g_s[NN_MAX];
__device__ float g_v[NN_MAX * 6];
__device__ float g_vus[NN_MAX * 8];
__device__ float g_agg[NN_MAX * 20];
__device__ float g_nhat[NE_MAX * 4];
__device__ float g_radial[NE_MAX * 8];
__device__ float g_mix[NE_MAX * 8];

#define INV_SQRT2 0.70710678118654752f
#define INV_SQRT3 0.57735026918962576f
#define INV_SQRT5 0.44721359549995794f
#define INV_SQRT8 0.35355339059327376f
#define SQRT2_F   1.4142135623730951f
#define C121_F    2.1213203435596424f
#define SQRT3_F   1.7320508075688772f

__device__ __forceinline__ float swishf(float x) {
    return x / (1.0f + __expf(-x));
}

// ---- tf32 split (3xTF32): hi = rna(x), lo = x - hi (exact in f32) ----
__device__ __forceinline__ void tf32split(float x, uint32_t& hi, uint32_t& lo) {
    asm("cvt.rna.tf32.f32 %0, %1;" : "=r"(hi) : "f"(x));
    lo = __float_as_uint(x - __uint_as_float(hi));
}

// ---- legacy warp MMA: m16n8k8 tf32 (sm_80+ path, works on sm_103) ----
__device__ __forceinline__ void mma8(float d[4], const uint32_t a[4],
                                     uint32_t b0, uint32_t b1) {
    asm volatile(
        "mma.sync.aligned.m16n8k8.row.col.f32.tf32.tf32.f32 "
        "{%0,%1,%2,%3}, {%4,%5,%6,%7}, {%8,%9}, {%0,%1,%2,%3};"
        : "+f"(d[0]), "+f"(d[1]), "+f"(d[2]), "+f"(d[3])
        : "r"(a[0]), "r"(a[1]), "r"(a[2]), "r"(a[3]), "r"(b0), "r"(b1));
}

// Gather A-fragment (k-tile kk) from D/h fragment registers via shfl.
// h4 = this thread's h values of tile kk: {(g,2t4),(g,2t4+1),(g+8,2t4),(g+8,2t4+1)}
// Output a[4] = {h(g,8kk+t4), h(g+8,8kk+t4), h(g,8kk+4+t4), h(g+8,8kk+4+t4)}
__device__ __forceinline__ void gather_a(float out[4], const float h4[4],
                                         int g, int t4) {
    int s0 = 4 * g + (t4 >> 1);
    int s2 = s0 + 2;
    float v00 = __shfl_sync(0xFFFFFFFFu, h4[0], s0);
    float v01 = __shfl_sync(0xFFFFFFFFu, h4[1], s0);
    float v02 = __shfl_sync(0xFFFFFFFFu, h4[2], s0);
    float v03 = __shfl_sync(0xFFFFFFFFu, h4[3], s0);
    float v20 = __shfl_sync(0xFFFFFFFFu, h4[0], s2);
    float v21 = __shfl_sync(0xFFFFFFFFu, h4[1], s2);
    float v22 = __shfl_sync(0xFFFFFFFFu, h4[2], s2);
    float v23 = __shfl_sync(0xFFFFFFFFu, h4[3], s2);
    bool p = (t4 & 1) != 0;
    out[0] = p ? v01 : v00;
    out[1] = p ? v03 : v02;
    out[2] = p ? v21 : v20;
    out[3] = p ? v23 : v22;
}

// ---------------------------------------------------------------------------
// init node state
// ---------------------------------------------------------------------------
__global__ void k_init(const float* __restrict__ nf, int nn) {
    int n = blockIdx.x * blockDim.x + threadIdx.x;
    if (n >= nn) return;
    g_s[n] = nf[n * 7];
#pragma unroll
    for (int i = 0; i < 6; i++) g_v[n * 6 + i] = nf[n * 7 + 1 + i];
}

// ---------------------------------------------------------------------------
// per-edge geometry
// ---------------------------------------------------------------------------
__global__ void k_geom(const float* __restrict__ pos,
                       const int* __restrict__ snd,
                       const int* __restrict__ rcv, int ne) {
    int e = blockIdx.x * blockDim.x + threadIdx.x;
    if (e >= ne) return;
    int s = snd[e], r = rcv[e];
    float vx = pos[r * 3 + 0] - pos[s * 3 + 0];
    float vy = pos[r * 3 + 1] - pos[s * 3 + 1];
    float vz = pos[r * 3 + 2] - pos[s * 3 + 2];
    float len = sqrtf(vx * vx + vy * vy + vz * vz);
    float inv = (len == 0.0f) ? 1.0f : (1.0f / len);
    *(float4*)&g_nhat[e * 4] = make_float4(vx * inv, vy * inv, vz * inv, 0.0f);

    float env = 0.0f;
    if (len < 1.0f) {
        float x = len;
        float x2 = x * x, x3 = x2 * x;
        float x6 = x3 * x3, x7 = x6 * x, x8 = x7 * x;
        env = 1.0f - 28.0f * x6 + 48.0f * x7 - 21.0f * x8;
    }
    float coef = (len == 0.0f) ? 0.0f : (SQRT2_F * env * inv);

    float s1, c1;
    sincospif(len, &s1, &c1);
    float out[8];
    float sm1 = 0.0f, sk = s1;
#pragma unroll
    for (int k = 0; k < 8; k++) {
        out[k] = sk * coef;
        float nx = 2.0f * c1 * sk - sm1;
        sm1 = sk; sk = nx;
    }
    *(float4*)&g_radial[e * 8]     = make_float4(out[0], out[1], out[2], out[3]);
    *(float4*)&g_radial[e * 8 + 4] = make_float4(out[4], out[5], out[6], out[7]);
}

// ---------------------------------------------------------------------------
// radial MLP via mma.sync m16n8k8 tf32 (3xTF32 split).
// Warp tile: 16 edges. Weights pre-packed in smem in B-fragment layout
// (one LDS.64 -> {b0,b1}). D->A reshuffles via shfl (no staging smem).
// Persistent grid; per-CTA weight prepack amortized over ~26 tiles.
// ---------------------------------------------------------------------------
__global__ __launch_bounds__(128)
void k_mix_mma(const float* __restrict__ W1, const float* __restrict__ W2,
               const float* __restrict__ W3, int ne, int ntiles) {
    // B-fragment packs: [tile][lane] -> (b0,b1) as one ull. hi & lo splits.
    __shared__ ull sB1h[8 * 32],  sB1l[8 * 32];    // W1: 8 n-tiles
    __shared__ ull sB2h[64 * 32], sB2l[64 * 32];   // W2: (kk,j) 64 tiles
    __shared__ ull sB3h[8 * 32],  sB3l[8 * 32];    // W3: 8 k-tiles (N=8)

    int tid = threadIdx.x;

    // ---- prepack W1 (scale 1/sqrt8 folded) ----
    for (int idx = tid; idx < 256; idx += 128) {
        int j = idx >> 5, l = idx & 31;
        float w0 = W1[(l & 3) * 64 + 8 * j + (l >> 2)] * INV_SQRT8;
        float w1 = W1[((l & 3) + 4) * 64 + 8 * j + (l >> 2)] * INV_SQRT8;
        uint32_t h0, l0, h1, l1;
        tf32split(w0, h0, l0); tf32split(w1, h1, l1);
        sB1h[idx] = ((ull)h1 << 32) | h0;
        sB1l[idx] = ((ull)l1 << 32) | l0;
    }
    // ---- prepack W2 (scale 0.125 folded) ----
    for (int idx = tid; idx < 2048; idx += 128) {
        int t = idx >> 5, l = idx & 31;
        int kk = t >> 3, j = t & 7;
        float w0 = W2[(8 * kk + (l & 3)) * 64 + 8 * j + (l >> 2)] * 0.125f;
        float w1 = W2[(8 * kk + (l & 3) + 4) * 64 + 8 * j + (l >> 2)] * 0.125f;
        uint32_t h0, l0, h1, l1;
        tf32split(w0, h0, l0); tf32split(w1, h1, l1);
        sB2h[idx] = ((ull)h1 << 32) | h0;
        sB2l[idx] = ((ull)l1 << 32) | l0;
    }
    // ---- prepack W3 (scale 0.125 folded) ----
    for (int idx = tid; idx < 256; idx += 128) {
        int kk = idx >> 5, l = idx & 31;
        float w0 = W3[(8 * kk + (l & 3)) * 8 + (l >> 2)] * 0.125f;
        float w1 = W3[(8 * kk + (l & 3) + 4) * 8 + (l >> 2)] * 0.125f;
        uint32_t h0, l0, h1, l1;
        tf32split(w0, h0, l0); tf32split(w1, h1, l1);
        sB3h[idx] = ((ull)h1 << 32) | h0;
        sB3l[idx] = ((ull)l1 << 32) | l0;
    }
    __syncthreads();

    int w    = tid >> 5;          // warp in CTA (4)
    int lane = tid & 31;
    int g    = lane >> 2;         // group id (row within 8)
    int t4   = lane & 3;          // thread-in-group

    for (int tile = blockIdx.x; tile < ntiles; tile += gridDim.x) {
        int base = tile * 64 + w * 16;
        int eg  = base + g;      if (eg  >= ne) eg  = ne - 1;
        int eg8 = base + g + 8;  if (eg8 >= ne) eg8 = ne - 1;

        // ===== phase 1: h1 = swish(radial @ W1s) =====
        uint32_t ah[4], al[4];
        {
            float r0 = g_radial[eg  * 8 + t4];
            float r1 = g_radial[eg8 * 8 + t4];
            float r2 = g_radial[eg  * 8 + t4 + 4];
            float r3 = g_radial[eg8 * 8 + t4 + 4];
            tf32split(r0, ah[0], al[0]);
            tf32split(r1, ah[1], al[1]);
            tf32split(r2, ah[2], al[2]);
            tf32split(r3, ah[3], al[3]);
        }
        float hj[8][4];
#pragma unroll
        for (int j = 0; j < 8; j++) {
            float D[4] = {0.f, 0.f, 0.f, 0.f};
            ull bh = sB1h[j * 32 + lane];
            ull bl = sB1l[j * 32 + lane];
            uint32_t bh0 = (uint32_t)bh, bh1 = (uint32_t)(bh >> 32);
            uint32_t bl0 = (uint32_t)bl, bl1 = (uint32_t)(bl >> 32);
            mma8(D, ah, bh0, bh1);
            mma8(D, al, bh0, bh1);
            mma8(D, ah, bl0, bl1);
            hj[j][0] = swishf(D[0]);
            hj[j][1] = swishf(D[1]);
            hj[j][2] = swishf(D[2]);
            hj[j][3] = swishf(D[3]);
        }

        // ===== phase 2: h2 = swish(h1 @ W2s) =====
        float D2[8][4];
#pragma unroll
        for (int j = 0; j < 8; j++)
#pragma unroll
            for (int q = 0; q < 4; q++) D2[j][q] = 0.f;

#pragma unroll
        for (int kk = 0; kk < 8; kk++) {
            float af[4];
            gather_a(af, hj[kk], g, t4);
            uint32_t ah2[4], al2[4];
#pragma unroll
            for (int q = 0; q < 4; q++) tf32split(af[q], ah2[q], al2[q]);
#pragma unroll
            for (int j = 0; j < 8; j++) {
                ull bh = sB2h[(kk * 8 + j) * 32 + lane];
                ull bl = sB2l[(kk * 8 + j) * 32 + lane];
                uint32_t bh0 = (uint32_t)bh, bh1 = (uint32_t)(bh >> 32);
                uint32_t bl0 = (uint32_t)bl, bl1 = (uint32_t)(bl >> 32);
                mma8(D2[j], ah2, bh0, bh1);
                mma8(D2[j], al2, bh0, bh1);
                mma8(D2[j], ah2, bl0, bl1);
            }
        }
        float hj2[8][4];
#pragma unroll
        for (int j = 0; j < 8; j++) {
            hj2[j][0] = swishf(D2[j][0]);
            hj2[j][1] = swishf(D2[j][1]);
            hj2[j][2] = swishf(D2[j][2]);
            hj2[j][3] = swishf(D2[j][3]);
        }

        // ===== phase 3: mix = h2 @ W3s (N=8), two chains for ILP =====
        float D3a[4] = {0.f, 0.f, 0.f, 0.f};
        float D3b[4] = {0.f, 0.f, 0.f, 0.f};
#pragma unroll
        for (int kk = 0; kk < 8; kk++) {
            float af[4];
            gather_a(af, hj2[kk], g, t4);
            uint32_t ah3[4], al3[4];
#pragma unroll
            for (int q = 0; q < 4; q++) tf32split(af[q], ah3[q], al3[q]);
            ull bh = sB3h[kk * 32 + lane];
            ull bl = sB3l[kk * 32 + lane];
            uint32_t bh0 = (uint32_t)bh, bh1 = (uint32_t)(bh >> 32);
            uint32_t bl0 = (uint32_t)bl, bl1 = (uint32_t)(bl >> 32);
            float* Dc = (kk & 1) ? D3b : D3a;
            mma8(Dc, ah3, bh0, bh1);
            mma8(Dc, al3, bh0, bh1);
            mma8(Dc, ah3, bl0, bl1);
        }
        float o0 = D3a[0] + D3b[0];
        float o1 = D3a[1] + D3b[1];
        float o2 = D3a[2] + D3b[2];
        float o3 = D3a[3] + D3b[3];

        int e0 = base + g, e1 = base + g + 8;
        if (e0 < ne) *(float2*)&g_mix[e0 * 8 + 2 * t4] = make_float2(o0, o1);
        if (e1 < ne) *(float2*)&g_mix[e1 * 8 + 2 * t4] = make_float2(o2, o3);
    }
}

// ---------------------------------------------------------------------------
// node pre
// ---------------------------------------------------------------------------
__global__ void k_node_pre(const float* __restrict__ Wus,
                           const float* __restrict__ Wuv, int nn) {
    int n = blockIdx.x * blockDim.x + threadIdx.x;
    if (n >= nn) return;
    float s = g_s[n];
    float su = s * Wus[0];
    float w00 = Wuv[0], w01 = Wuv[1], w10 = Wuv[2], w11 = Wuv[3];
    float vu0[3], vu1[3];
#pragma unroll
    for (int c = 0; c < 3; c++) {
        float a = g_v[n * 6 + c], b = g_v[n * 6 + 3 + c];
        vu0[c] = (a * w00 + b * w10) * INV_SQRT2;
        vu1[c] = (a * w01 + b * w11) * INV_SQRT2;
    }
    *(float4*)&g_vus[n * 8]     = make_float4(vu0[0], vu0[1], vu0[2], su);
    *(float4*)&g_vus[n * 8 + 4] = make_float4(vu1[0], vu1[1], vu1[2], 0.0f);
    float4 z = make_float4(0.f, 0.f, 0.f, 0.f);
#pragma unroll
    for (int i = 0; i < 5; i++) *(float4*)&g_agg[n * 20 + 4 * i] = z;
}

// ---------------------------------------------------------------------------
// per-edge message + vectorized scatter
// ---------------------------------------------------------------------------
__global__ void k_edge(const int* __restrict__ snd,
                       const int* __restrict__ rcv, int ne) {
    int e = blockIdx.x * blockDim.x + threadIdx.x;
    if (e >= ne) return;
    int s = snd[e], r = rcv[e];
    float4 nh = *(const float4*)&g_nhat[e * 4];
    float nx = nh.x, ny = nh.y, nz = nh.z;
    float4 m0 = *(const float4*)&g_mix[e * 8];
    float4 m1 = *(const float4*)&g_mix[e * 8 + 4];

    float4 p0 = *(const float4*)&g_vus[s * 8];
    float4 p1 = *(const float4*)&g_vus[s * 8 + 4];
    float se = p0.w;
    float v0x = p0.x, v0y = p0.y, v0z = p0.z;
    float v1x = p1.x, v1y = p1.y, v1z = p1.z;

    float d0 = v0x * nx + v0y * ny + v0z * nz;
    float d1 = v1x * nx + v1y * ny + v1z * nz;

    const float third = 1.0f / 3.0f;
    float c0 = C121_F * m1.y;
    float c1 = C121_F * m1.z;
    float cb = SQRT3_F * se * m1.w;

    float m_[18];
    m_[0]  = se * m0.x;
    m_[1]  = d0 * m0.y;
    m_[2]  = d1 * m0.z;
    m_[3]  = v0x * m0.w;  m_[4]  = v0y * m0.w;  m_[5]  = v0z * m0.w;
    m_[6]  = v1x * m1.x;  m_[7]  = v1y * m1.x;  m_[8]  = v1z * m1.x;
    m_[9]  = c0 * (d0 * nx - v0x * third);
    m_[10] = c0 * (d0 * ny - v0y * third);
    m_[11] = c0 * (d0 * nz - v0z * third);
    m_[12] = c1 * (d1 * nx - v1x * third);
    m_[13] = c1 * (d1 * ny - v1y * third);
    m_[14] = c1 * (d1 * nz - v1z * third);
    m_[15] = cb * nx;  m_[16] = cb * ny;  m_[17] = cb * nz;

    float* base = &g_agg[r * 20];
#pragma unroll
    for (int q = 0; q < 4; q++) {
        asm volatile("red.global.add.v4.f32 [%0], {%1, %2, %3, %4};"
                     :: "l"(base + 4 * q),
                        "f"(m_[4 * q + 0]), "f"(m_[4 * q + 1]),
                        "f"(m_[4 * q + 2]), "f"(m_[4 * q + 3])
                     : "memory");
    }
    asm volatile("red.global.add.v2.f32 [%0], {%1, %2};"
                 :: "l"(base + 16), "f"(m_[16]), "f"(m_[17]) : "memory");
}

// ---------------------------------------------------------------------------
// node post
// ---------------------------------------------------------------------------
__global__ void k_node_post(const float* __restrict__ Wss,
                            const float* __restrict__ Wsv,
                            const float* __restrict__ Wds,
                            const float* __restrict__ Wdv,
                            float* __restrict__ out, int write_out, int nn) {
    int n = blockIdx.x * blockDim.x + threadIdx.x;
    if (n >= nn) return;
    float s = g_s[n];
    float v[6];
#pragma unroll
    for (int i = 0; i < 6; i++) v[i] = g_v[n * 6 + i];
    float agg[18];
#pragma unroll
    for (int i = 0; i < 18; i++) agg[i] = g_agg[n * 20 + i];

    float st[3];
#pragma unroll
    for (int k = 0; k < 3; k++) {
        float sd = (agg[0] * Wds[0 * 3 + k] + agg[1] * Wds[1 * 3 + k] +
                    agg[2] * Wds[2 * 3 + k]) * INV_SQRT3;
        st[k] = sd + s * Wss[k];
    }
    float vt[6];
#pragma unroll
    for (int k = 0; k < 2; k++) {
#pragma unroll
        for (int c = 0; c < 3; c++) {
            float vd = 0.0f;
#pragma unroll
            for (int m = 0; m < 5; m++) vd = fmaf(agg[3 + m * 3 + c], Wdv[m * 2 + k], vd);
            vd *= INV_SQRT5;
            float vsc = (v[c] * Wsv[0 * 2 + k] + v[3 + c] * Wsv[1 * 2 + k]) * INV_SQRT2;
            vt[k * 3 + c] = vd + vsc;
        }
    }
    float ns = swishf(st[0]);
    float g1 = swishf(st[1]);
    float g2 = swishf(st[2]);
    g_s[n] = ns;
#pragma unroll
    for (int c = 0; c < 3; c++) {
        float nv0 = vt[c] * g1;
        float nv1 = vt[3 + c] * g2;
        g_v[n * 6 + c]     = nv0;
        g_v[n * 6 + 3 + c] = nv1;
        if (write_out) out[n * 3 + c] = nv0;
    }
}

// ---------------------------------------------------------------------------
// launch
// ---------------------------------------------------------------------------
extern "C" void kernel_launch(void* const* d_in, const int* in_sizes, int n_in,
                              void* d_out, int out_size) {
    const float* pos = (const float*)d_in[0];
    const float* nf  = (const float*)d_in[1];
    const int* snd   = (const int*)d_in[2];
    const int* rcv   = (const int*)d_in[3];
    const float* Wss = (const float*)d_in[4];
    const float* Wsv = (const float*)d_in[5];
    const float* Wus = (const float*)d_in[6];
    const float* Wuv = (const float*)d_in[7];
    const float* W1  = (const float*)d_in[8];
    const float* W2  = (const float*)d_in[9];
    const float* W3  = (const float*)d_in[10];
    const float* Wds = (const float*)d_in[11];
    const float* Wdv = (const float*)d_in[12];
    float* out = (float*)d_out;

    int ne = in_sizes[2];
    int nn = in_sizes[0] / 3;

    int nb_n = (nn + 255) / 256;
    int nb_e = (ne + 255) / 256;
    int ntiles = (ne + 63) / 64;              // 64 edges per CTA-tile (16/warp)
    int nb_t = ntiles < 592 ? ntiles : 592;   // persistent

    k_init<<<nb_n, 256>>>(nf, nn);
    k_geom<<<nb_e, 256>>>(pos, snd, rcv, ne);

    for (int l = 0; l < 3; l++) {
        k_node_pre<<<nb_n, 256>>>(Wus + l * 1, Wuv + l * 4, nn);
        k_mix_mma<<<nb_t, 128>>>(W1 + l * 512, W2 + l * 4096, W3 + l * 512, ne, ntiles);
        k_edge<<<nb_e, 256>>>(snd, rcv, ne);
        k_node_post<<<nb_n, 256>>>(Wss + l * 3, Wsv + l * 4, Wds + l * 9,
                                   Wdv + l * 10, out, (l == 2) ? 1 : 0, nn);
    }
}

// round 9
// speedup vs baseline: 2.3584x; 1.3443x over previous
#include <cuda_runtime.h>
#include <cuda_bf16.h>
#include <math.h>
#include <stdint.h>

typedef unsigned long long ull;

#define NN_MAX 50000
#define NE_MAX 1000000

// ---- device-global scratch (no allocations allowed) ----
__device__ float g_s[NN_MAX];
__device__ float g_v[NN_MAX * 6];
__device__ float g_vus[NN_MAX * 8];
__device__ float g_agg[NN_MAX * 20];
__device__ float g_nhat[NE_MAX * 4];
__device__ float g_radial[NE_MAX * 8];
__device__ float g_mix[NE_MAX * 8];

#define INV_SQRT2 0.70710678118654752f
#define INV_SQRT3 0.57735026918962576f
#define INV_SQRT5 0.44721359549995794f
#define INV_SQRT8 0.35355339059327376f
#define SQRT2_F   1.4142135623730951f
#define C121_F    2.1213203435596424f
#define SQRT3_F   1.7320508075688772f

__device__ __forceinline__ float swishf(float x) {
    return x / (1.0f + __expf(-x));
}

// ---- tf32 split (phase 1) ----
__device__ __forceinline__ void tf32split(float x, uint32_t& hi, uint32_t& lo) {
    asm("cvt.rna.tf32.f32 %0, %1;" : "=r"(hi) : "f"(x));
    lo = __float_as_uint(x - __uint_as_float(hi));
}

// ---- bf16 2-way split, packed pair (x -> low half, y -> high half) ----
__device__ __forceinline__ void bfsplit2(float x, float y,
                                         uint32_t& hp, uint32_t& lp) {
    __nv_bfloat16 xb = __float2bfloat16(x);
    __nv_bfloat16 yb = __float2bfloat16(y);
    float xr = x - __bfloat162float(xb);
    float yr = y - __bfloat162float(yb);
    __nv_bfloat16 xl = __float2bfloat16(xr);
    __nv_bfloat16 yl = __float2bfloat16(yr);
    __nv_bfloat162 h2 = __halves2bfloat162(xb, yb);
    __nv_bfloat162 l2 = __halves2bfloat162(xl, yl);
    hp = *reinterpret_cast<uint32_t*>(&h2);
    lp = *reinterpret_cast<uint32_t*>(&l2);
}
__device__ __forceinline__ uint32_t bfpack(float x, float y) {
    __nv_bfloat162 h2 = __halves2bfloat162(__float2bfloat16(x), __float2bfloat16(y));
    return *reinterpret_cast<uint32_t*>(&h2);
}

// ---- warp MMAs ----
__device__ __forceinline__ void mma8(float d[4], const uint32_t a[4],
                                     uint32_t b0, uint32_t b1) {
    asm volatile(
        "mma.sync.aligned.m16n8k8.row.col.f32.tf32.tf32.f32 "
        "{%0,%1,%2,%3}, {%4,%5,%6,%7}, {%8,%9}, {%0,%1,%2,%3};"
        : "+f"(d[0]), "+f"(d[1]), "+f"(d[2]), "+f"(d[3])
        : "r"(a[0]), "r"(a[1]), "r"(a[2]), "r"(a[3]), "r"(b0), "r"(b1));
}
__device__ __forceinline__ void mma16(float d[4], const uint32_t a[4],
                                      uint32_t b0, uint32_t b1) {
    asm volatile(
        "mma.sync.aligned.m16n8k16.row.col.f32.bf16.bf16.f32 "
        "{%0,%1,%2,%3}, {%4,%5,%6,%7}, {%8,%9}, {%0,%1,%2,%3};"
        : "+f"(d[0]), "+f"(d[1]), "+f"(d[2]), "+f"(d[3])
        : "r"(a[0]), "r"(a[1]), "r"(a[2]), "r"(a[3]), "r"(b0), "r"(b1));
}

// ---------------------------------------------------------------------------
// init node state
// ---------------------------------------------------------------------------
__global__ void k_init(const float* __restrict__ nf, int nn) {
    int n = blockIdx.x * blockDim.x + threadIdx.x;
    if (n >= nn) return;
    g_s[n] = nf[n * 7];
#pragma unroll
    for (int i = 0; i < 6; i++) g_v[n * 6 + i] = nf[n * 7 + 1 + i];
}

// ---------------------------------------------------------------------------
// per-edge geometry
// ---------------------------------------------------------------------------
__global__ void k_geom(const float* __restrict__ pos,
                       const int* __restrict__ snd,
                       const int* __restrict__ rcv, int ne) {
    int e = blockIdx.x * blockDim.x + threadIdx.x;
    if (e >= ne) return;
    int s = snd[e], r = rcv[e];
    float vx = pos[r * 3 + 0] - pos[s * 3 + 0];
    float vy = pos[r * 3 + 1] - pos[s * 3 + 1];
    float vz = pos[r * 3 + 2] - pos[s * 3 + 2];
    float len = sqrtf(vx * vx + vy * vy + vz * vz);
    float inv = (len == 0.0f) ? 1.0f : (1.0f / len);
    *(float4*)&g_nhat[e * 4] = make_float4(vx * inv, vy * inv, vz * inv, 0.0f);

    float env = 0.0f;
    if (len < 1.0f) {
        float x = len;
        float x2 = x * x, x3 = x2 * x;
        float x6 = x3 * x3, x7 = x6 * x, x8 = x7 * x;
        env = 1.0f - 28.0f * x6 + 48.0f * x7 - 21.0f * x8;
    }
    float coef = (len == 0.0f) ? 0.0f : (SQRT2_F * env * inv);

    float s1, c1;
    sincospif(len, &s1, &c1);
    float out[8];
    float sm1 = 0.0f, sk = s1;
#pragma unroll
    for (int k = 0; k < 8; k++) {
        out[k] = sk * coef;
        float nx = 2.0f * c1 * sk - sm1;
        sm1 = sk; sk = nx;
    }
    *(float4*)&g_radial[e * 8]     = make_float4(out[0], out[1], out[2], out[3]);
    *(float4*)&g_radial[e * 8 + 4] = make_float4(out[4], out[5], out[6], out[7]);
}

// ---------------------------------------------------------------------------
// radial MLP: phase1 tf32 m16n8k8 (3-term), phases 2-3 bf16 m16n8k16
// (2-way split, 3 terms). The k16 A-fragment equals the concatenation of the
// D-fragments of two adjacent N=8 tiles -> NO shuffles between stages.
// Warp tile = 16 edges. Persistent grid.
// ---------------------------------------------------------------------------
__global__ __launch_bounds__(128)
void k_mix_mma(const float* __restrict__ W1, const float* __restrict__ W2,
               const float* __restrict__ W3, int ne, int ntiles) {
    __shared__ ull sB1h[8 * 32],  sB1l[8 * 32];    // W1 tf32 packs (8 n-tiles)
    __shared__ ull sB2h[32 * 32], sB2l[32 * 32];   // W2 bf16 packs (4kk x 8j)
    __shared__ ull sB3h[4 * 32],  sB3l[4 * 32];    // W3 bf16 packs (4 kk)

    int tid = threadIdx.x;

    // ---- prepack W1 (tf32 split; scale 1/sqrt8 folded) ----
    for (int idx = tid; idx < 256; idx += 128) {
        int j = idx >> 5, l = idx & 31;
        float w0 = W1[(l & 3) * 64 + 8 * j + (l >> 2)] * INV_SQRT8;
        float w1 = W1[((l & 3) + 4) * 64 + 8 * j + (l >> 2)] * INV_SQRT8;
        uint32_t h0, l0, h1, l1;
        tf32split(w0, h0, l0); tf32split(w1, h1, l1);
        sB1h[idx] = ((ull)h1 << 32) | h0;
        sB1l[idx] = ((ull)l1 << 32) | l0;
    }
    // ---- prepack W2 (bf16 split; scale 0.125 folded) ----
    // tile t = kk*8 + j; lane l: g=l>>2, t4=l&3; col = 8j+g
    // b0 = rows (16kk+2t4, +1), b1 = rows (16kk+2t4+8, +9)
    for (int idx = tid; idx < 1024; idx += 128) {
        int t = idx >> 5, l = idx & 31;
        int kk = t >> 3, j = t & 7;
        int g = l >> 2, t4 = l & 3;
        int col = 8 * j + g;
        int r0 = 16 * kk + 2 * t4;
        float w00 = W2[(r0 + 0) * 64 + col] * 0.125f;
        float w01 = W2[(r0 + 1) * 64 + col] * 0.125f;
        float w10 = W2[(r0 + 8) * 64 + col] * 0.125f;
        float w11 = W2[(r0 + 9) * 64 + col] * 0.125f;
        uint32_t b0h, b0l, b1h, b1l;
        bfsplit2(w00, w01, b0h, b0l);
        bfsplit2(w10, w11, b1h, b1l);
        sB2h[idx] = ((ull)b1h << 32) | b0h;
        sB2l[idx] = ((ull)b1l << 32) | b0l;
    }
    // ---- prepack W3 (bf16 split; scale 0.125 folded) ----
    for (int idx = tid; idx < 128; idx += 128) {
        int kk = idx >> 5, l = idx & 31;
        int g = l >> 2, t4 = l & 3;
        int r0 = 16 * kk + 2 * t4;
        float w00 = W3[(r0 + 0) * 8 + g] * 0.125f;
        float w01 = W3[(r0 + 1) * 8 + g] * 0.125f;
        float w10 = W3[(r0 + 8) * 8 + g] * 0.125f;
        float w11 = W3[(r0 + 9) * 8 + g] * 0.125f;
        uint32_t b0h, b0l, b1h, b1l;
        bfsplit2(w00, w01, b0h, b0l);
        bfsplit2(w10, w11, b1h, b1l);
        sB3h[idx] = ((ull)b1h << 32) | b0h;
        sB3l[idx] = ((ull)b1l << 32) | b0l;
    }
    __syncthreads();

    int w    = tid >> 5;
    int lane = tid & 31;
    int g    = lane >> 2;
    int t4   = lane & 3;

    for (int tile = blockIdx.x; tile < ntiles; tile += gridDim.x) {
        int base = tile * 64 + w * 16;
        int eg  = base + g;      if (eg  >= ne) eg  = ne - 1;
        int eg8 = base + g + 8;  if (eg8 >= ne) eg8 = ne - 1;

        // ===== phase 1 (tf32): h1 = swish(radial @ W1s) =====
        uint32_t ah[4], al[4];
        {
            float r0 = g_radial[eg  * 8 + t4];
            float r1 = g_radial[eg8 * 8 + t4];
            float r2 = g_radial[eg  * 8 + t4 + 4];
            float r3 = g_radial[eg8 * 8 + t4 + 4];
            tf32split(r0, ah[0], al[0]);
            tf32split(r1, ah[1], al[1]);
            tf32split(r2, ah[2], al[2]);
            tf32split(r3, ah[3], al[3]);
        }
        float hj[8][4];
#pragma unroll
        for (int j = 0; j < 8; j++) {
            float D[4] = {0.f, 0.f, 0.f, 0.f};
            ull bh = sB1h[j * 32 + lane];
            ull bl = sB1l[j * 32 + lane];
            uint32_t bh0 = (uint32_t)bh, bh1 = (uint32_t)(bh >> 32);
            uint32_t bl0 = (uint32_t)bl, bl1 = (uint32_t)(bl >> 32);
            mma8(D, ah, bh0, bh1);
            mma8(D, al, bh0, bh1);
            mma8(D, ah, bl0, bl1);
            hj[j][0] = swishf(D[0]);
            hj[j][1] = swishf(D[1]);
            hj[j][2] = swishf(D[2]);
            hj[j][3] = swishf(D[3]);
        }

        // ===== phase 2 (bf16 k16): h2 = swish(h1 @ W2s) =====
        float D2[8][4];
#pragma unroll
        for (int j = 0; j < 8; j++)
#pragma unroll
            for (int q = 0; q < 4; q++) D2[j][q] = 0.f;

#pragma unroll
        for (int kk = 0; kk < 4; kk++) {
            // A-frag = D-frags of tiles 2kk (k 0-7) and 2kk+1 (k 8-15)
            uint32_t a2h[4], a2l[4];
            bfsplit2(hj[2 * kk][0],     hj[2 * kk][1],     a2h[0], a2l[0]);
            bfsplit2(hj[2 * kk][2],     hj[2 * kk][3],     a2h[1], a2l[1]);
            bfsplit2(hj[2 * kk + 1][0], hj[2 * kk + 1][1], a2h[2], a2l[2]);
            bfsplit2(hj[2 * kk + 1][2], hj[2 * kk + 1][3], a2h[3], a2l[3]);
#pragma unroll
            for (int j = 0; j < 8; j++) {
                ull bh = sB2h[(kk * 8 + j) * 32 + lane];
                ull bl = sB2l[(kk * 8 + j) * 32 + lane];
                uint32_t bh0 = (uint32_t)bh, bh1 = (uint32_t)(bh >> 32);
                uint32_t bl0 = (uint32_t)bl, bl1 = (uint32_t)(bl >> 32);
                mma16(D2[j], a2h, bh0, bh1);
                mma16(D2[j], a2l, bh0, bh1);
                mma16(D2[j], a2h, bl0, bl1);
            }
        }
        float hj2[8][4];
#pragma unroll
        for (int j = 0; j < 8; j++) {
            hj2[j][0] = swishf(D2[j][0]);
            hj2[j][1] = swishf(D2[j][1]);
            hj2[j][2] = swishf(D2[j][2]);
            hj2[j][3] = swishf(D2[j][3]);
        }

        // ===== phase 3 (bf16 k16): mix = h2 @ W3s (N=8) =====
        float D3a[4] = {0.f, 0.f, 0.f, 0.f};
        float D3b[4] = {0.f, 0.f, 0.f, 0.f};
#pragma unroll
        for (int kk = 0; kk < 4; kk++) {
            uint32_t a3h[4], a3l[4];
            bfsplit2(hj2[2 * kk][0],     hj2[2 * kk][1],     a3h[0], a3l[0]);
            bfsplit2(hj2[2 * kk][2],     hj2[2 * kk][3],     a3h[1], a3l[1]);
            bfsplit2(hj2[2 * kk + 1][0], hj2[2 * kk + 1][1], a3h[2], a3l[2]);
            bfsplit2(hj2[2 * kk + 1][2], hj2[2 * kk + 1][3], a3h[3], a3l[3]);
            ull bh = sB3h[kk * 32 + lane];
            ull bl = sB3l[kk * 32 + lane];
            uint32_t bh0 = (uint32_t)bh, bh1 = (uint32_t)(bh >> 32);
            uint32_t bl0 = (uint32_t)bl, bl1 = (uint32_t)(bl >> 32);
            float* Dc = (kk & 1) ? D3b : D3a;
            mma16(Dc, a3h, bh0, bh1);
            mma16(Dc, a3l, bh0, bh1);
            mma16(Dc, a3h, bl0, bl1);
        }
        float o0 = D3a[0] + D3b[0];
        float o1 = D3a[1] + D3b[1];
        float o2 = D3a[2] + D3b[2];
        float o3 = D3a[3] + D3b[3];

        int e0 = base + g, e1 = base + g + 8;
        if (e0 < ne) *(float2*)&g_mix[e0 * 8 + 2 * t4] = make_float2(o0, o1);
        if (e1 < ne) *(float2*)&g_mix[e1 * 8 + 2 * t4] = make_float2(o2, o3);
    }
}

// ---------------------------------------------------------------------------
// node pre
// ---------------------------------------------------------------------------
__global__ void k_node_pre(const float* __restrict__ Wus,
                           const float* __restrict__ Wuv, int nn) {
    int n = blockIdx.x * blockDim.x + threadIdx.x;
    if (n >= nn) return;
    float s = g_s[n];
    float su = s * Wus[0];
    float w00 = Wuv[0], w01 = Wuv[1], w10 = Wuv[2], w11 = Wuv[3];
    float vu0[3], vu1[3];
#pragma unroll
    for (int c = 0; c < 3; c++) {
        float a = g_v[n * 6 + c], b = g_v[n * 6 + 3 + c];
        vu0[c] = (a * w00 + b * w10) * INV_SQRT2;
        vu1[c] = (a * w01 + b * w11) * INV_SQRT2;
    }
    *(float4*)&g_vus[n * 8]     = make_float4(vu0[0], vu0[1], vu0[2], su);
    *(float4*)&g_vus[n * 8 + 4] = make_float4(vu1[0], vu1[1], vu1[2], 0.0f);
    float4 z = make_float4(0.f, 0.f, 0.f, 0.f);
#pragma unroll
    for (int i = 0; i < 5; i++) *(float4*)&g_agg[n * 20 + 4 * i] = z;
}

// ---------------------------------------------------------------------------
// per-edge message + vectorized scatter
// ---------------------------------------------------------------------------
__global__ void k_edge(const int* __restrict__ snd,
                       const int* __restrict__ rcv, int ne) {
    int e = blockIdx.x * blockDim.x + threadIdx.x;
    if (e >= ne) return;
    int s = snd[e], r = rcv[e];
    float4 nh = *(const float4*)&g_nhat[e * 4];
    float nx = nh.x, ny = nh.y, nz = nh.z;
    float4 m0 = *(const float4*)&g_mix[e * 8];
    float4 m1 = *(const float4*)&g_mix[e * 8 + 4];

    float4 p0 = *(const float4*)&g_vus[s * 8];
    float4 p1 = *(const float4*)&g_vus[s * 8 + 4];
    float se = p0.w;
    float v0x = p0.x, v0y = p0.y, v0z = p0.z;
    float v1x = p1.x, v1y = p1.y, v1z = p1.z;

    float d0 = v0x * nx + v0y * ny + v0z * nz;
    float d1 = v1x * nx + v1y * ny + v1z * nz;

    const float third = 1.0f / 3.0f;
    float c0 = C121_F * m1.y;
    float c1 = C121_F * m1.z;
    float cb = SQRT3_F * se * m1.w;

    float m_[18];
    m_[0]  = se * m0.x;
    m_[1]  = d0 * m0.y;
    m_[2]  = d1 * m0.z;
    m_[3]  = v0x * m0.w;  m_[4]  = v0y * m0.w;  m_[5]  = v0z * m0.w;
    m_[6]  = v1x * m1.x;  m_[7]  = v1y * m1.x;  m_[8]  = v1z * m1.x;
    m_[9]  = c0 * (d0 * nx - v0x * third);
    m_[10] = c0 * (d0 * ny - v0y * third);
    m_[11] = c0 * (d0 * nz - v0z * third);
    m_[12] = c1 * (d1 * nx - v1x * third);
    m_[13] = c1 * (d1 * ny - v1y * third);
    m_[14] = c1 * (d1 * nz - v1z * third);
    m_[15] = cb * nx;  m_[16] = cb * ny;  m_[17] = cb * nz;

    float* base = &g_agg[r * 20];
#pragma unroll
    for (int q = 0; q < 4; q++) {
        asm volatile("red.global.add.v4.f32 [%0], {%1, %2, %3, %4};"
                     :: "l"(base + 4 * q),
                        "f"(m_[4 * q + 0]), "f"(m_[4 * q + 1]),
                        "f"(m_[4 * q + 2]), "f"(m_[4 * q + 3])
                     : "memory");
    }
    asm volatile("red.global.add.v2.f32 [%0], {%1, %2};"
                 :: "l"(base + 16), "f"(m_[16]), "f"(m_[17]) : "memory");
}

// ---------------------------------------------------------------------------
// node post
// ---------------------------------------------------------------------------
__global__ void k_node_post(const float* __restrict__ Wss,
                            const float* __restrict__ Wsv,
                            const float* __restrict__ Wds,
                            const float* __restrict__ Wdv,
                            float* __restrict__ out, int write_out, int nn) {
    int n = blockIdx.x * blockDim.x + threadIdx.x;
    if (n >= nn) return;
    float s = g_s[n];
    float v[6];
#pragma unroll
    for (int i = 0; i < 6; i++) v[i] = g_v[n * 6 + i];
    float agg[18];
#pragma unroll
    for (int i = 0; i < 18; i++) agg[i] = g_agg[n * 20 + i];

    float st[3];
#pragma unroll
    for (int k = 0; k < 3; k++) {
        float sd = (agg[0] * Wds[0 * 3 + k] + agg[1] * Wds[1 * 3 + k] +
                    agg[2] * Wds[2 * 3 + k]) * INV_SQRT3;
        st[k] = sd + s * Wss[k];
    }
    float vt[6];
#pragma unroll
    for (int k = 0; k < 2; k++) {
#pragma unroll
        for (int c = 0; c < 3; c++) {
            float vd = 0.0f;
#pragma unroll
            for (int m = 0; m < 5; m++) vd = fmaf(agg[3 + m * 3 + c], Wdv[m * 2 + k], vd);
            vd *= INV_SQRT5;
            float vsc = (v[c] * Wsv[0 * 2 + k] + v[3 + c] * Wsv[1 * 2 + k]) * INV_SQRT2;
            vt[k * 3 + c] = vd + vsc;
        }
    }
    float ns = swishf(st[0]);
    float g1 = swishf(st[1]);
    float g2 = swishf(st[2]);
    g_s[n] = ns;
#pragma unroll
    for (int c = 0; c < 3; c++) {
        float nv0 = vt[c] * g1;
        float nv1 = vt[3 + c] * g2;
        g_v[n * 6 + c]     = nv0;
        g_v[n * 6 + 3 + c] = nv1;
        if (write_out) out[n * 3 + c] = nv0;
    }
}

// ---------------------------------------------------------------------------
// launch
// ---------------------------------------------------------------------------
extern "C" void kernel_launch(void* const* d_in, const int* in_sizes, int n_in,
                              void* d_out, int out_size) {
    const float* pos = (const float*)d_in[0];
    const float* nf  = (const float*)d_in[1];
    const int* snd   = (const int*)d_in[2];
    const int* rcv   = (const int*)d_in[3];
    const float* Wss = (const float*)d_in[4];
    const float* Wsv = (const float*)d_in[5];
    const float* Wus = (const float*)d_in[6];
    const float* Wuv = (const float*)d_in[7];
    const float* W1  = (const float*)d_in[8];
    const float* W2  = (const float*)d_in[9];
    const float* W3  = (const float*)d_in[10];
    const float* Wds = (const float*)d_in[11];
    const float* Wdv = (const float*)d_in[12];
    float* out = (float*)d_out;

    int ne = in_sizes[2];
    int nn = in_sizes[0] / 3;

    int nb_n = (nn + 255) / 256;
    int nb_e = (ne + 255) / 256;
    int ntiles = (ne + 63) / 64;              // 64 edges per CTA (16/warp)
    int nb_t = ntiles < 740 ? ntiles : 740;   // persistent, ~5 CTAs/SM

    k_init<<<nb_n, 256>>>(nf, nn);
    k_geom<<<nb_e, 256>>>(pos, snd, rcv, ne);

    for (int l = 0; l < 3; l++) {
        k_node_pre<<<nb_n, 256>>>(Wus + l * 1, Wuv + l * 4, nn);
        k_mix_mma<<<nb_t, 128>>>(W1 + l * 512, W2 + l * 4096, W3 + l * 512, ne, ntiles);
        k_edge<<<nb_e, 256>>>(snd, rcv, ne);
        k_node_post<<<nb_n, 256>>>(Wss + l * 3, Wsv + l * 4, Wds + l * 9,
                                   Wdv + l * 10, out, (l == 2) ? 1 : 0, nn);
    }
}